// round 1
// baseline (speedup 1.0000x reference)
#include <cuda_runtime.h>
#include <math.h>

// ---------------------------------------------------------------------------
// CrossTransformerBlock3D: 32x32x32 voxels, DIM=192, 12 heads x 16, WS=(2,2,2)
// Pipeline:
//  1. xn = LN(x), xan = LN(xa)
//  2. q  = xn  @ Wq  + bq         [32768,192]
//     kv = xan @ Wkv + bkv        [32768,384]   (computed per-token, gathered per window)
//  3. windowed cross attention -> g_attn (voxel layout == window-reversed)
//  4. x1 = x + g_attn @ Wp + bp
//  5. x1n = LN2(x1)
//  6. h  = gelu(x1n @ W1 + b1)    [32768,384]
//  7. out = x1 + h @ W2 + b2      -> d_out
// ---------------------------------------------------------------------------

#define TOKENS 32768
#define DIM 192
#define HID 384
#define HEADS 12
#define HD 16

__device__ float g_xn  [TOKENS * DIM];
__device__ float g_xan [TOKENS * DIM];
__device__ float g_q   [TOKENS * DIM];
__device__ float g_kv  [TOKENS * HID];
__device__ float g_attn[TOKENS * DIM];
__device__ float g_x1  [TOKENS * DIM];
__device__ float g_x1n [TOKENS * DIM];
__device__ float g_h   [TOKENS * HID];

// --------------------------- LayerNorm (warp per row, C=192) ----------------
__global__ void ln_kernel(const float* __restrict__ x, const float* __restrict__ g,
                          const float* __restrict__ b, float* __restrict__ o, int rows)
{
    int warp = (blockIdx.x * blockDim.x + threadIdx.x) >> 5;
    int lane = threadIdx.x & 31;
    if (warp >= rows) return;
    const float* xr = x + (size_t)warp * DIM;
    float v[6];
    float s = 0.f, s2 = 0.f;
#pragma unroll
    for (int i = 0; i < 6; i++) {
        v[i] = xr[lane + i * 32];
        s += v[i];
        s2 += v[i] * v[i];
    }
#pragma unroll
    for (int off = 16; off; off >>= 1) {
        s  += __shfl_xor_sync(0xffffffffu, s,  off);
        s2 += __shfl_xor_sync(0xffffffffu, s2, off);
    }
    float mean = s * (1.f / DIM);
    float var  = s2 * (1.f / DIM) - mean * mean;
    float rstd = rsqrtf(var + 1e-5f);
    float* orow = o + (size_t)warp * DIM;
#pragma unroll
    for (int i = 0; i < 6; i++) {
        int c = lane + i * 32;
        orow[c] = (v[i] - mean) * rstd * g[c] + b[c];
    }
}

// --------------------------- fp32 tiled GEMM 64x64x16 -----------------------
// C[M,N] = A[M,K] @ B[K,N] + bias (+ optional GELU, + optional residual)
template <bool RES, bool GELU>
__global__ void gemm_kernel(const float* __restrict__ A, const float* __restrict__ B,
                            const float* __restrict__ bias, const float* __restrict__ resid,
                            float* __restrict__ C, int M, int N, int K)
{
    __shared__ float As[16][64];
    __shared__ float Bs[16][64];
    const int tid = threadIdx.x;            // 128 threads
    const int bm = blockIdx.y * 64;
    const int bn = blockIdx.x * 64;
    const int ty = tid >> 3;                // 0..15 -> 4 rows each
    const int tx = tid & 7;                 // 0..7  -> 8 cols each
    float acc[4][8];
#pragma unroll
    for (int r = 0; r < 4; r++)
#pragma unroll
        for (int c = 0; c < 8; c++) acc[r][c] = 0.f;

    for (int k0 = 0; k0 < K; k0 += 16) {
#pragma unroll
        for (int i = 0; i < 2; i++) {
            int f = tid * 2 + i;            // 0..255
            // A tile: 64 rows x 16 k, stored transposed As[k][m]
            int r = f >> 2, kq = f & 3;
            float4 a = *(const float4*)&A[(size_t)(bm + r) * K + k0 + kq * 4];
            As[kq * 4 + 0][r] = a.x;
            As[kq * 4 + 1][r] = a.y;
            As[kq * 4 + 2][r] = a.z;
            As[kq * 4 + 3][r] = a.w;
            // B tile: 16 k x 64 n
            int kr = f >> 4, nq = f & 15;
            *(float4*)&Bs[kr][nq * 4] = *(const float4*)&B[(size_t)(k0 + kr) * N + bn + nq * 4];
        }
        __syncthreads();
#pragma unroll
        for (int k = 0; k < 16; k++) {
            float4 a4 = *(const float4*)&As[k][ty * 4];
            float4 b0 = *(const float4*)&Bs[k][tx * 8];
            float4 b1 = *(const float4*)&Bs[k][tx * 8 + 4];
            float av[4] = {a4.x, a4.y, a4.z, a4.w};
            float bv[8] = {b0.x, b0.y, b0.z, b0.w, b1.x, b1.y, b1.z, b1.w};
#pragma unroll
            for (int r = 0; r < 4; r++)
#pragma unroll
                for (int c = 0; c < 8; c++) acc[r][c] += av[r] * bv[c];
        }
        __syncthreads();
    }

#pragma unroll
    for (int r = 0; r < 4; r++) {
        int row = bm + ty * 4 + r;
#pragma unroll
        for (int c = 0; c < 8; c++) {
            int col = bn + tx * 8 + c;
            float v = acc[r][c] + bias[col];
            if (GELU) v = 0.5f * v * (1.f + erff(v * 0.70710678118654752f));
            if (RES)  v += resid[(size_t)row * N + col];
            C[(size_t)row * N + col] = v;
        }
    }
}

// --------------------------- windowed cross attention -----------------------
// One block per window (4096). 128 threads: 96 compute threads (head, query),
// all 128 stage K/V slabs. Online softmax; invalid slabs folded analytically
// (k = bkv_k, v = bkv_v for every padded key).
__global__ void attn_kernel(const float* __restrict__ q, const float* __restrict__ kv,
                            const float* __restrict__ bkv, float* __restrict__ out)
{
    __shared__ float q_sh[8 * DIM];     // 6 KB
    __shared__ float kv_sh[8 * HID];    // 12 KB (one neighbor slab: 8 tokens x (k|v))

    const int bid = blockIdx.x;
    const int wd = bid >> 8, wh = (bid >> 4) & 15, ww = bid & 15;
    const int tid = threadIdx.x;

    // stage q for this window's 8 tokens (voxel-indexed rows)
    for (int f = tid; f < 8 * 48; f += 128) {       // 1536 floats / 4
        int t = f / 48, c4 = f % 48;
        int vox = ((wd * 2 + (t >> 2)) * 32 + wh * 2 + ((t >> 1) & 1)) * 32 + ww * 2 + (t & 1);
        *(float4*)&q_sh[t * DIM + c4 * 4] = *(const float4*)&q[(size_t)vox * DIM + c4 * 4];
    }
    __syncthreads();

    const int h = tid >> 3, qi = tid & 7;
    const bool active = tid < 96;
    float qr[16], acc[16], m = 0.f, l = 0.f, s_pad = 0.f;
    if (active) {
#pragma unroll
        for (int d = 0; d < 16; d++) {
            qr[d] = q_sh[qi * DIM + h * HD + d] * 0.25f;   // scale = HD^-0.5
            s_pad += qr[d] * bkv[h * HD + d];
            acc[d] = 0.f;
        }
        m = s_pad;          // pad score always participates (slab 20 always invalid)
    }

    int pad_slabs = 0;
    for (int sl = 0; sl < 27; sl++) {
        int nd = wd + sl / 9 - 1;
        int nh = wh + (sl / 3) % 3 - 1;
        int nw = ww + sl % 3 - 1;
        bool valid = (sl != 20) && (unsigned)nd < 16u && (unsigned)nh < 16u && (unsigned)nw < 16u;
        if (!valid) { pad_slabs++; continue; }
        __syncthreads();
        for (int f = tid; f < 8 * 96; f += 128) {   // 3072 floats / 4
            int t = f / 96, c4 = f % 96;
            int vox = ((nd * 2 + (t >> 2)) * 32 + nh * 2 + ((t >> 1) & 1)) * 32 + nw * 2 + (t & 1);
            *(float4*)&kv_sh[t * HID + c4 * 4] = *(const float4*)&kv[(size_t)vox * HID + c4 * 4];
        }
        __syncthreads();
        if (active) {
#pragma unroll
            for (int t = 0; t < 8; t++) {
                const float* kp = &kv_sh[t * HID + h * HD];
                float sc = 0.f;
#pragma unroll
                for (int d = 0; d < 16; d++) sc += qr[d] * kp[d];
                if (sc > m) {
                    float cf = __expf(m - sc);
                    l *= cf;
#pragma unroll
                    for (int d = 0; d < 16; d++) acc[d] *= cf;
                    m = sc;
                }
                float p = __expf(sc - m);
                l += p;
                const float* vp = kp + DIM;
#pragma unroll
                for (int d = 0; d < 16; d++) acc[d] += p * vp[d];
            }
        }
    }

    if (active) {
        float pp = __expf(s_pad - m) * (8.f * (float)pad_slabs);
        l += pp;
#pragma unroll
        for (int d = 0; d < 16; d++) acc[d] += pp * bkv[DIM + h * HD + d];
        float inv = 1.f / l;
        int vox = ((wd * 2 + (qi >> 2)) * 32 + wh * 2 + ((qi >> 1) & 1)) * 32 + ww * 2 + (qi & 1);
#pragma unroll
        for (int d = 0; d < 16; d++)
            out[(size_t)vox * DIM + h * HD + d] = acc[d] * inv;
    }
}

// ---------------------------------------------------------------------------
extern "C" void kernel_launch(void* const* d_in, const int* in_sizes, int n_in,
                              void* d_out, int out_size)
{
    const float* x       = (const float*)d_in[0];
    const float* xa      = (const float*)d_in[1];
    const float* norm1_g = (const float*)d_in[2];
    const float* norm1_b = (const float*)d_in[3];
    const float* norm2_g = (const float*)d_in[4];
    const float* norm2_b = (const float*)d_in[5];
    const float* Wq      = (const float*)d_in[6];
    const float* bq      = (const float*)d_in[7];
    const float* Wkv     = (const float*)d_in[8];
    const float* bkv     = (const float*)d_in[9];
    const float* Wp      = (const float*)d_in[10];
    const float* bp      = (const float*)d_in[11];
    const float* W1      = (const float*)d_in[12];
    const float* b1      = (const float*)d_in[13];
    const float* W2      = (const float*)d_in[14];
    const float* b2      = (const float*)d_in[15];
    float* out = (float*)d_out;

    float* xn   = nullptr; float* xan  = nullptr; float* qb  = nullptr; float* kvb = nullptr;
    float* attn = nullptr; float* x1   = nullptr; float* x1n = nullptr; float* hb  = nullptr;
    cudaGetSymbolAddress((void**)&xn,   g_xn);
    cudaGetSymbolAddress((void**)&xan,  g_xan);
    cudaGetSymbolAddress((void**)&qb,   g_q);
    cudaGetSymbolAddress((void**)&kvb,  g_kv);
    cudaGetSymbolAddress((void**)&attn, g_attn);
    cudaGetSymbolAddress((void**)&x1,   g_x1);
    cudaGetSymbolAddress((void**)&x1n,  g_x1n);
    cudaGetSymbolAddress((void**)&hb,   g_h);

    const int ln_blocks = TOKENS / 8;                 // 8 rows per 256-thread block

    // 1. LayerNorms of x and xa
    ln_kernel<<<ln_blocks, 256>>>(x,  norm1_g, norm1_b, xn,  TOKENS);
    ln_kernel<<<ln_blocks, 256>>>(xa, norm1_g, norm1_b, xan, TOKENS);

    // 2. q and kv projections
    gemm_kernel<false, false><<<dim3(DIM / 64, TOKENS / 64), 128>>>(xn,  Wq,  bq,  nullptr, qb,  TOKENS, DIM, DIM);
    gemm_kernel<false, false><<<dim3(HID / 64, TOKENS / 64), 128>>>(xan, Wkv, bkv, nullptr, kvb, TOKENS, HID, DIM);

    // 3. windowed cross attention
    attn_kernel<<<4096, 128>>>(qb, kvb, bkv, attn);

    // 4. projection + residual: x1 = x + attn @ Wp + bp
    gemm_kernel<true, false><<<dim3(DIM / 64, TOKENS / 64), 128>>>(attn, Wp, bp, x, x1, TOKENS, DIM, DIM);

    // 5. LN2
    ln_kernel<<<ln_blocks, 256>>>(x1, norm2_g, norm2_b, x1n, TOKENS);

    // 6. MLP up + gelu
    gemm_kernel<false, true><<<dim3(HID / 64, TOKENS / 64), 128>>>(x1n, W1, b1, nullptr, hb, TOKENS, HID, DIM);

    // 7. MLP down + residual -> out
    gemm_kernel<true, false><<<dim3(DIM / 64, TOKENS / 64), 128>>>(hb, W2, b2, x1, out, TOKENS, DIM, HID);
}

// round 2
// speedup vs baseline: 2.0979x; 2.0979x over previous
#include <cuda_runtime.h>
#include <math.h>

// ---------------------------------------------------------------------------
// CrossTransformerBlock3D: 32x32x32 voxels, DIM=192, 12 heads x 16, WS=(2,2,2)
//  1. xn = LN(x), xan = LN(xa)
//  2. q = xn @ Wq + bq ; kv = xan @ Wkv + bkv  (per-token, gathered per window)
//  3. windowed cross attention -> g_attn
//  4. x1 = x + g_attn @ Wp + bp
//  5. x1n = LN2(x1);  h = gelu(x1n @ W1 + b1);  out = x1 + h @ W2 + b2
// GEMMs: tf32 tensor-core mma.m16n8k8, 128x64 block tile, double-buffered.
// ---------------------------------------------------------------------------

#define TOKENS 32768
#define DIM 192
#define HID 384
#define HEADS 12
#define HD 16

__device__ float g_xn  [TOKENS * DIM];
__device__ float g_xan [TOKENS * DIM];
__device__ float g_q   [TOKENS * DIM];
__device__ float g_kv  [TOKENS * HID];
__device__ float g_attn[TOKENS * DIM];
__device__ float g_x1  [TOKENS * DIM];
__device__ float g_x1n [TOKENS * DIM];
__device__ float g_h   [TOKENS * HID];

// --------------------------- LayerNorm (warp per row, C=192) ----------------
__global__ void ln_kernel(const float* __restrict__ x, const float* __restrict__ g,
                          const float* __restrict__ b, float* __restrict__ o, int rows)
{
    int warp = (blockIdx.x * blockDim.x + threadIdx.x) >> 5;
    int lane = threadIdx.x & 31;
    if (warp >= rows) return;
    const float* xr = x + (size_t)warp * DIM;
    float v[6];
    float s = 0.f, s2 = 0.f;
#pragma unroll
    for (int i = 0; i < 6; i++) {
        v[i] = xr[lane + i * 32];
        s += v[i];
        s2 += v[i] * v[i];
    }
#pragma unroll
    for (int off = 16; off; off >>= 1) {
        s  += __shfl_xor_sync(0xffffffffu, s,  off);
        s2 += __shfl_xor_sync(0xffffffffu, s2, off);
    }
    float mean = s * (1.f / DIM);
    float var  = s2 * (1.f / DIM) - mean * mean;
    float rstd = rsqrtf(var + 1e-5f);
    float* orow = o + (size_t)warp * DIM;
#pragma unroll
    for (int i = 0; i < 6; i++) {
        int c = lane + i * 32;
        orow[c] = (v[i] - mean) * rstd * g[c] + b[c];
    }
}

// --------------------------- tf32 tensor-core GEMM --------------------------
// C[M,N] = A[M,K] @ B[K,N] + bias (+GELU) (+residual). Block tile 128x64,
// 8 warps (4x2), warp tile 32x32, K-step 16 (2x m16n8k8), double-buffered smem.
#define MMA_TF32(d, a, b)                                                     \
    asm volatile("mma.sync.aligned.m16n8k8.row.col.f32.tf32.tf32.f32 "        \
                 "{%0,%1,%2,%3}, {%4,%5,%6,%7}, {%8,%9}, {%0,%1,%2,%3};"      \
                 : "+f"(d[0]), "+f"(d[1]), "+f"(d[2]), "+f"(d[3])             \
                 : "r"(a[0]), "r"(a[1]), "r"(a[2]), "r"(a[3]),                \
                   "r"(b[0]), "r"(b[1]))

template <bool RES, bool GELU>
__global__ __launch_bounds__(256) void gemm_tc(const float* __restrict__ A,
                                               const float* __restrict__ B,
                                               const float* __restrict__ bias,
                                               const float* __restrict__ resid,
                                               float* __restrict__ C,
                                               int M, int N, int K)
{
    __shared__ __align__(16) float As[2][128][20];   // [m][k], stride 20: conflict-free frag loads
    __shared__ __align__(16) float Bs[2][16][72];    // [k][n], stride 72

    const int tid = threadIdx.x;
    const int bm = blockIdx.y * 128;
    const int bn = blockIdx.x * 64;
    const int lane = tid & 31, w = tid >> 5;
    const int g = lane >> 2, tg = lane & 3;
    const int wr = (w & 3) * 32;          // warp row in block tile
    const int wc = (w >> 2) * 32;         // warp col in block tile

    float acc[2][4][4];
#pragma unroll
    for (int mi = 0; mi < 2; mi++)
#pragma unroll
        for (int ni = 0; ni < 4; ni++)
#pragma unroll
            for (int r = 0; r < 4; r++) acc[mi][ni][r] = 0.f;

    // staging thread mapping (coalesced)
    const int ar = tid >> 2, ac = (tid & 3) * 4;        // A: rows ar, ar+64; k-cols ac..ac+3
    const int bkr = tid >> 4, bnq = (tid & 15) * 4;     // B: k-row bkr; n-cols bnq..bnq+3

    float4 pa0 = *(const float4*)&A[(size_t)(bm + ar) * K + ac];
    float4 pa1 = *(const float4*)&A[(size_t)(bm + ar + 64) * K + ac];
    float4 pb  = *(const float4*)&B[(size_t)bkr * N + bn + bnq];

    int s = 0;
    for (int k0 = 0; k0 < K; k0 += 16, s ^= 1) {
        As[s][ar][ac + 0] = pa0.x;  As[s][ar][ac + 1] = pa0.y;
        As[s][ar][ac + 2] = pa0.z;  As[s][ar][ac + 3] = pa0.w;
        As[s][ar + 64][ac + 0] = pa1.x;  As[s][ar + 64][ac + 1] = pa1.y;
        As[s][ar + 64][ac + 2] = pa1.z;  As[s][ar + 64][ac + 3] = pa1.w;
        *(float4*)&Bs[s][bkr][bnq] = pb;
        __syncthreads();

        if (k0 + 16 < K) {
            pa0 = *(const float4*)&A[(size_t)(bm + ar) * K + k0 + 16 + ac];
            pa1 = *(const float4*)&A[(size_t)(bm + ar + 64) * K + k0 + 16 + ac];
            pb  = *(const float4*)&B[(size_t)(k0 + 16 + bkr) * N + bn + bnq];
        }

#pragma unroll
        for (int kk = 0; kk < 2; kk++) {
            unsigned a[2][4], b[4][2];
#pragma unroll
            for (int mi = 0; mi < 2; mi++) {
                int r = wr + mi * 16 + g;
                a[mi][0] = __float_as_uint(As[s][r    ][kk * 8 + tg]);
                a[mi][1] = __float_as_uint(As[s][r + 8][kk * 8 + tg]);
                a[mi][2] = __float_as_uint(As[s][r    ][kk * 8 + tg + 4]);
                a[mi][3] = __float_as_uint(As[s][r + 8][kk * 8 + tg + 4]);
            }
#pragma unroll
            for (int ni = 0; ni < 4; ni++) {
                int n = wc + ni * 8 + g;
                b[ni][0] = __float_as_uint(Bs[s][kk * 8 + tg    ][n]);
                b[ni][1] = __float_as_uint(Bs[s][kk * 8 + tg + 4][n]);
            }
#pragma unroll
            for (int mi = 0; mi < 2; mi++)
#pragma unroll
                for (int ni = 0; ni < 4; ni++)
                    MMA_TF32(acc[mi][ni], a[mi], b[ni]);
        }
    }

    // epilogue
#pragma unroll
    for (int mi = 0; mi < 2; mi++) {
#pragma unroll
        for (int ni = 0; ni < 4; ni++) {
            int col = bn + wc + ni * 8 + tg * 2;
            float b0 = bias[col], b1 = bias[col + 1];
#pragma unroll
            for (int half = 0; half < 2; half++) {
                int row = bm + wr + mi * 16 + g + half * 8;
                float v0 = acc[mi][ni][half * 2 + 0] + b0;
                float v1 = acc[mi][ni][half * 2 + 1] + b1;
                if (GELU) {
                    v0 = 0.5f * v0 * (1.f + erff(v0 * 0.70710678118654752f));
                    v1 = 0.5f * v1 * (1.f + erff(v1 * 0.70710678118654752f));
                }
                if (RES) {
                    v0 += resid[(size_t)row * N + col];
                    v1 += resid[(size_t)row * N + col + 1];
                }
                float2 o = make_float2(v0, v1);
                *(float2*)&C[(size_t)row * N + col] = o;
            }
        }
    }
}

// --------------------------- windowed cross attention -----------------------
// One block per window (4096). 96 compute threads (head,query); all 128 stage.
// Double-buffered slab staging: prefetch slab i+1 into registers while
// computing slab i. Invalid slabs folded analytically (k=bkv_k, v=bkv_v).
__global__ __launch_bounds__(128) void attn_kernel(const float* __restrict__ q,
                                                   const float* __restrict__ kv,
                                                   const float* __restrict__ bkv,
                                                   float* __restrict__ out)
{
    __shared__ float q_sh[8 * DIM];           // 6 KB
    __shared__ float kv_sh[2][8 * HID];       // 24 KB (double buffer)

    const int bid = blockIdx.x;
    const int wd = bid >> 8, wh = (bid >> 4) & 15, ww = bid & 15;
    const int tid = threadIdx.x;

    // stage q for this window's 8 tokens
    for (int f = tid; f < 8 * 48; f += 128) {
        int t = f / 48, c4 = f % 48;
        int vox = ((wd * 2 + (t >> 2)) * 32 + wh * 2 + ((t >> 1) & 1)) * 32 + ww * 2 + (t & 1);
        *(float4*)&q_sh[t * DIM + c4 * 4] = *(const float4*)&q[(size_t)vox * DIM + c4 * 4];
    }

    // enumerate valid neighbor slabs (identical across threads)
    int vlist[26], nv = 0, npad = 0;
#pragma unroll
    for (int sl = 0; sl < 27; sl++) {
        int nd = wd + sl / 9 - 1;
        int nh = wh + (sl / 3) % 3 - 1;
        int nw = ww + sl % 3 - 1;
        bool valid = (sl != 20) && (unsigned)nd < 16u && (unsigned)nh < 16u && (unsigned)nw < 16u;
        if (valid) vlist[nv++] = (nd << 8) | (nh << 4) | nw;
        else       npad++;
    }

    // per-thread staging lanes: 6 float4 per slab (768 float4 total / 128 thr)
    int st_t[6], st_c4[6], st_voxbase[6];
#pragma unroll
    for (int j = 0; j < 6; j++) {
        int f = tid + j * 128;
        st_t[j] = f / 96;
        st_c4[j] = f % 96;
    }

    // preload slab 0
    float4 stg[6];
    {
        int e = vlist[0];
        int nd = e >> 8, nh = (e >> 4) & 15, nw = e & 15;
#pragma unroll
        for (int j = 0; j < 6; j++) {
            int t = st_t[j];
            int vox = ((nd * 2 + (t >> 2)) * 32 + nh * 2 + ((t >> 1) & 1)) * 32 + nw * 2 + (t & 1);
            stg[j] = *(const float4*)&kv[(size_t)vox * HID + st_c4[j] * 4];
        }
    }
#pragma unroll
    for (int j = 0; j < 6; j++)
        *(float4*)&kv_sh[0][st_t[j] * HID + st_c4[j] * 4] = stg[j];
    __syncthreads();

    const int h = tid >> 3, qi = tid & 7;
    const bool active = tid < 96;
    float qr[16], accv[16], m = 0.f, l = 0.f, s_pad = 0.f;
    if (active) {
#pragma unroll
        for (int d = 0; d < 16; d++) {
            qr[d] = q_sh[qi * DIM + h * HD + d] * 0.25f;   // scale = HD^-0.5
            s_pad += qr[d] * bkv[h * HD + d];
            accv[d] = 0.f;
        }
        m = s_pad;    // pad score always participates (slab 20 always invalid)
    }

    int cur = 0;
    for (int i = 0; i < nv; i++) {
        // prefetch next slab into registers
        if (i + 1 < nv) {
            int e = vlist[i + 1];
            int nd = e >> 8, nh = (e >> 4) & 15, nw = e & 15;
#pragma unroll
            for (int j = 0; j < 6; j++) {
                int t = st_t[j];
                int vox = ((nd * 2 + (t >> 2)) * 32 + nh * 2 + ((t >> 1) & 1)) * 32 + nw * 2 + (t & 1);
                stg[j] = *(const float4*)&kv[(size_t)vox * HID + st_c4[j] * 4];
            }
        }

        if (active) {
#pragma unroll
            for (int t = 0; t < 8; t++) {
                const float* kp = &kv_sh[cur][t * HID + h * HD];
                float sc = 0.f;
#pragma unroll
                for (int d = 0; d < 16; d++) sc += qr[d] * kp[d];
                if (sc > m) {
                    float cf = __expf(m - sc);
                    l *= cf;
#pragma unroll
                    for (int d = 0; d < 16; d++) accv[d] *= cf;
                    m = sc;
                }
                float p = __expf(sc - m);
                l += p;
                const float* vp = kp + DIM;
#pragma unroll
                for (int d = 0; d < 16; d++) accv[d] += p * vp[d];
            }
        }
        __syncthreads();
        if (i + 1 < nv) {
#pragma unroll
            for (int j = 0; j < 6; j++)
                *(float4*)&kv_sh[cur ^ 1][st_t[j] * HID + st_c4[j] * 4] = stg[j];
        }
        __syncthreads();
        cur ^= 1;
    }

    if (active) {
        float pp = __expf(s_pad - m) * (8.f * (float)npad);
        l += pp;
#pragma unroll
        for (int d = 0; d < 16; d++) accv[d] += pp * bkv[DIM + h * HD + d];
        float inv = 1.f / l;
        int vox = ((wd * 2 + (qi >> 2)) * 32 + wh * 2 + ((qi >> 1) & 1)) * 32 + ww * 2 + (qi & 1);
#pragma unroll
        for (int d = 0; d < 16; d++)
            out[(size_t)vox * DIM + h * HD + d] = accv[d] * inv;
    }
}

// ---------------------------------------------------------------------------
extern "C" void kernel_launch(void* const* d_in, const int* in_sizes, int n_in,
                              void* d_out, int out_size)
{
    const float* x       = (const float*)d_in[0];
    const float* xa      = (const float*)d_in[1];
    const float* norm1_g = (const float*)d_in[2];
    const float* norm1_b = (const float*)d_in[3];
    const float* norm2_g = (const float*)d_in[4];
    const float* norm2_b = (const float*)d_in[5];
    const float* Wq      = (const float*)d_in[6];
    const float* bq      = (const float*)d_in[7];
    const float* Wkv     = (const float*)d_in[8];
    const float* bkv     = (const float*)d_in[9];
    const float* Wp      = (const float*)d_in[10];
    const float* bp      = (const float*)d_in[11];
    const float* W1      = (const float*)d_in[12];
    const float* b1      = (const float*)d_in[13];
    const float* W2      = (const float*)d_in[14];
    const float* b2      = (const float*)d_in[15];
    float* out = (float*)d_out;

    float* xn   = nullptr; float* xan  = nullptr; float* qb  = nullptr; float* kvb = nullptr;
    float* attn = nullptr; float* x1   = nullptr; float* x1n = nullptr; float* hb  = nullptr;
    cudaGetSymbolAddress((void**)&xn,   g_xn);
    cudaGetSymbolAddress((void**)&xan,  g_xan);
    cudaGetSymbolAddress((void**)&qb,   g_q);
    cudaGetSymbolAddress((void**)&kvb,  g_kv);
    cudaGetSymbolAddress((void**)&attn, g_attn);
    cudaGetSymbolAddress((void**)&x1,   g_x1);
    cudaGetSymbolAddress((void**)&x1n,  g_x1n);
    cudaGetSymbolAddress((void**)&hb,   g_h);

    const int ln_blocks = TOKENS / 8;

    ln_kernel<<<ln_blocks, 256>>>(x,  norm1_g, norm1_b, xn,  TOKENS);
    ln_kernel<<<ln_blocks, 256>>>(xa, norm1_g, norm1_b, xan, TOKENS);

    gemm_tc<false, false><<<dim3(DIM / 64, TOKENS / 128), 256>>>(xn,  Wq,  bq,  nullptr, qb,  TOKENS, DIM, DIM);
    gemm_tc<false, false><<<dim3(HID / 64, TOKENS / 128), 256>>>(xan, Wkv, bkv, nullptr, kvb, TOKENS, HID, DIM);

    attn_kernel<<<4096, 128>>>(qb, kvb, bkv, attn);

    gemm_tc<true, false><<<dim3(DIM / 64, TOKENS / 128), 256>>>(attn, Wp, bp, x, x1, TOKENS, DIM, DIM);

    ln_kernel<<<ln_blocks, 256>>>(x1, norm2_g, norm2_b, x1n, TOKENS);

    gemm_tc<false, true><<<dim3(HID / 64, TOKENS / 128), 256>>>(x1n, W1, b1, nullptr, hb, TOKENS, HID, DIM);
    gemm_tc<true, false><<<dim3(DIM / 64, TOKENS / 128), 256>>>(hb, W2, b2, x1, out, TOKENS, DIM, HID);
}

// round 3
// speedup vs baseline: 2.2310x; 1.0635x over previous
#include <cuda_runtime.h>
#include <math.h>

// ---------------------------------------------------------------------------
// CrossTransformerBlock3D: 32x32x32 voxels, DIM=192, 12 heads x 16, WS=(2,2,2)
// GEMMs: tf32 mma.m16n8k8, block tile 128x96, 4 warps (warp tile 64x48),
// cp.async double-buffered staging.
// ---------------------------------------------------------------------------

#define TOKENS 32768
#define DIM 192
#define HID 384
#define HEADS 12
#define HD 16

__device__ float g_xn  [TOKENS * DIM];
__device__ float g_xan [TOKENS * DIM];
__device__ float g_q   [TOKENS * DIM];
__device__ float g_kv  [TOKENS * HID];
__device__ float g_attn[TOKENS * DIM];
__device__ float g_x1  [TOKENS * DIM];
__device__ float g_x1n [TOKENS * DIM];
__device__ float g_h   [TOKENS * HID];

// --------------------------- LayerNorm (warp per row, C=192) ----------------
__global__ void ln_kernel(const float* __restrict__ x, const float* __restrict__ g,
                          const float* __restrict__ b, float* __restrict__ o, int rows)
{
    int warp = (blockIdx.x * blockDim.x + threadIdx.x) >> 5;
    int lane = threadIdx.x & 31;
    if (warp >= rows) return;
    const float* xr = x + (size_t)warp * DIM;
    float v[6];
    float s = 0.f, s2 = 0.f;
#pragma unroll
    for (int i = 0; i < 6; i++) {
        v[i] = xr[lane + i * 32];
        s += v[i];
        s2 += v[i] * v[i];
    }
#pragma unroll
    for (int off = 16; off; off >>= 1) {
        s  += __shfl_xor_sync(0xffffffffu, s,  off);
        s2 += __shfl_xor_sync(0xffffffffu, s2, off);
    }
    float mean = s * (1.f / DIM);
    float var  = s2 * (1.f / DIM) - mean * mean;
    float rstd = rsqrtf(var + 1e-5f);
    float* orow = o + (size_t)warp * DIM;
#pragma unroll
    for (int i = 0; i < 6; i++) {
        int c = lane + i * 32;
        orow[c] = (v[i] - mean) * rstd * g[c] + b[c];
    }
}

// --------------------------- cp.async helpers -------------------------------
__device__ __forceinline__ void cp16(void* dst_smem, const void* src)
{
    unsigned d = (unsigned)__cvta_generic_to_shared(dst_smem);
    asm volatile("cp.async.ca.shared.global [%0], [%1], 16;" :: "r"(d), "l"(src));
}
#define CP_COMMIT asm volatile("cp.async.commit_group;")
#define CP_WAIT0  asm volatile("cp.async.wait_group 0;")

// --------------------------- tf32 tensor-core GEMM --------------------------
// C[M,N] = A[M,K] @ B[K,N] + bias (+GELU) (+residual).
// Block 128x96, K-chunk 16, 4 warps: warp (w&1) -> row 64-half, (w>>1) -> col 48-quarter.
#define MMA_TF32(d, a, b)                                                     \
    asm volatile("mma.sync.aligned.m16n8k8.row.col.f32.tf32.tf32.f32 "        \
                 "{%0,%1,%2,%3}, {%4,%5,%6,%7}, {%8,%9}, {%0,%1,%2,%3};"      \
                 : "+f"(d[0]), "+f"(d[1]), "+f"(d[2]), "+f"(d[3])             \
                 : "r"(a[0]), "r"(a[1]), "r"(a[2]), "r"(a[3]),                \
                   "r"(b[0]), "r"(b[1]))

template <bool RES, bool GELU>
__global__ __launch_bounds__(128, 3) void gemm_tc(const float* __restrict__ A,
                                                  const float* __restrict__ B,
                                                  const float* __restrict__ bias,
                                                  const float* __restrict__ resid,
                                                  float* __restrict__ C,
                                                  int M, int N, int K)
{
    __shared__ __align__(16) float As[2][128][20];   // row stride 20 -> conflict-free
    __shared__ __align__(16) float Bs[2][16][104];   // row stride 104 (mod32=8) -> conflict-free

    const int tid = threadIdx.x;
    const int bm = blockIdx.y * 128;
    const int bn = blockIdx.x * 96;
    const int lane = tid & 31, w = tid >> 5;
    const int g = lane >> 2, tg = lane & 3;
    const int wr = (w & 1) * 64;
    const int wc = (w >> 1) * 48;

    float acc[4][6][4];
#pragma unroll
    for (int mi = 0; mi < 4; mi++)
#pragma unroll
        for (int ni = 0; ni < 6; ni++)
#pragma unroll
            for (int r = 0; r < 4; r++) acc[mi][ni][r] = 0.f;

    const int nchunks = K >> 4;

    // ---- staging lambda-free: chunk ci into buffer s
    // A: 512 float4 -> 4 per thread; B: 16x24 float4 -> 3 per thread
    {
        int k0 = 0;
#pragma unroll
        for (int i = 0; i < 4; i++) {
            int f = tid + i * 128;
            int r = f >> 2, c4 = (f & 3) * 4;
            cp16(&As[0][r][c4], &A[(size_t)(bm + r) * K + k0 + c4]);
        }
#pragma unroll
        for (int i = 0; i < 3; i++) {
            int f = tid + i * 128;
            int kr = f / 24, nq = (f % 24) * 4;
            cp16(&Bs[0][kr][nq], &B[(size_t)(k0 + kr) * N + bn + nq]);
        }
        CP_COMMIT;
    }

    int s = 0;
    for (int ci = 0; ci < nchunks; ci++, s ^= 1) {
        CP_WAIT0;
        __syncthreads();

        if (ci + 1 < nchunks) {
            int k0 = (ci + 1) << 4;
#pragma unroll
            for (int i = 0; i < 4; i++) {
                int f = tid + i * 128;
                int r = f >> 2, c4 = (f & 3) * 4;
                cp16(&As[s ^ 1][r][c4], &A[(size_t)(bm + r) * K + k0 + c4]);
            }
#pragma unroll
            for (int i = 0; i < 3; i++) {
                int f = tid + i * 128;
                int kr = f / 24, nq = (f % 24) * 4;
                cp16(&Bs[s ^ 1][kr][nq], &B[(size_t)(k0 + kr) * N + bn + nq]);
            }
            CP_COMMIT;
        }

#pragma unroll
        for (int kk = 0; kk < 2; kk++) {
            unsigned a[4][4], b[6][2];
#pragma unroll
            for (int mi = 0; mi < 4; mi++) {
                int r = wr + mi * 16 + g;
                a[mi][0] = __float_as_uint(As[s][r    ][kk * 8 + tg]);
                a[mi][1] = __float_as_uint(As[s][r + 8][kk * 8 + tg]);
                a[mi][2] = __float_as_uint(As[s][r    ][kk * 8 + tg + 4]);
                a[mi][3] = __float_as_uint(As[s][r + 8][kk * 8 + tg + 4]);
            }
#pragma unroll
            for (int ni = 0; ni < 6; ni++) {
                int n = wc + ni * 8 + g;
                b[ni][0] = __float_as_uint(Bs[s][kk * 8 + tg    ][n]);
                b[ni][1] = __float_as_uint(Bs[s][kk * 8 + tg + 4][n]);
            }
#pragma unroll
            for (int mi = 0; mi < 4; mi++)
#pragma unroll
                for (int ni = 0; ni < 6; ni++)
                    MMA_TF32(acc[mi][ni], a[mi], b[ni]);
        }
        __syncthreads();
    }

    // epilogue
#pragma unroll
    for (int mi = 0; mi < 4; mi++) {
#pragma unroll
        for (int ni = 0; ni < 6; ni++) {
            int col = bn + wc + ni * 8 + tg * 2;
            float b0 = bias[col], b1 = bias[col + 1];
#pragma unroll
            for (int half = 0; half < 2; half++) {
                int row = bm + wr + mi * 16 + g + half * 8;
                float v0 = acc[mi][ni][half * 2 + 0] + b0;
                float v1 = acc[mi][ni][half * 2 + 1] + b1;
                if (GELU) {
                    v0 = 0.5f * v0 * (1.f + erff(v0 * 0.70710678118654752f));
                    v1 = 0.5f * v1 * (1.f + erff(v1 * 0.70710678118654752f));
                }
                if (RES) {
                    v0 += resid[(size_t)row * N + col];
                    v1 += resid[(size_t)row * N + col + 1];
                }
                *(float2*)&C[(size_t)row * N + col] = make_float2(v0, v1);
            }
        }
    }
}

// --------------------------- windowed cross attention -----------------------
__global__ __launch_bounds__(128) void attn_kernel(const float* __restrict__ q,
                                                   const float* __restrict__ kv,
                                                   const float* __restrict__ bkv,
                                                   float* __restrict__ out)
{
    __shared__ float q_sh[8 * DIM];
    __shared__ float kv_sh[2][8 * HID];

    const int bid = blockIdx.x;
    const int wd = bid >> 8, wh = (bid >> 4) & 15, ww = bid & 15;
    const int tid = threadIdx.x;

    for (int f = tid; f < 8 * 48; f += 128) {
        int t = f / 48, c4 = f % 48;
        int vox = ((wd * 2 + (t >> 2)) * 32 + wh * 2 + ((t >> 1) & 1)) * 32 + ww * 2 + (t & 1);
        *(float4*)&q_sh[t * DIM + c4 * 4] = *(const float4*)&q[(size_t)vox * DIM + c4 * 4];
    }

    int vlist[26], nv = 0, npad = 0;
#pragma unroll
    for (int sl = 0; sl < 27; sl++) {
        int nd = wd + sl / 9 - 1;
        int nh = wh + (sl / 3) % 3 - 1;
        int nw = ww + sl % 3 - 1;
        bool valid = (sl != 20) && (unsigned)nd < 16u && (unsigned)nh < 16u && (unsigned)nw < 16u;
        if (valid) vlist[nv++] = (nd << 8) | (nh << 4) | nw;
        else       npad++;
    }

    int st_t[6], st_c4[6];
#pragma unroll
    for (int j = 0; j < 6; j++) {
        int f = tid + j * 128;
        st_t[j] = f / 96;
        st_c4[j] = f % 96;
    }

    float4 stg[6];
    {
        int e = vlist[0];
        int nd = e >> 8, nh = (e >> 4) & 15, nw = e & 15;
#pragma unroll
        for (int j = 0; j < 6; j++) {
            int t = st_t[j];
            int vox = ((nd * 2 + (t >> 2)) * 32 + nh * 2 + ((t >> 1) & 1)) * 32 + nw * 2 + (t & 1);
            stg[j] = *(const float4*)&kv[(size_t)vox * HID + st_c4[j] * 4];
        }
    }
#pragma unroll
    for (int j = 0; j < 6; j++)
        *(float4*)&kv_sh[0][st_t[j] * HID + st_c4[j] * 4] = stg[j];
    __syncthreads();

    const int h = tid >> 3, qi = tid & 7;
    const bool active = tid < 96;
    float4 qv[4];
    float accv[16], m = 0.f, l = 0.f, s_pad = 0.f;
    if (active) {
        const float4* bk4 = (const float4*)&bkv[h * HD];
#pragma unroll
        for (int p = 0; p < 4; p++) {
            float4 t4 = *(const float4*)&q_sh[qi * DIM + h * HD + p * 4];
            qv[p] = make_float4(t4.x * 0.25f, t4.y * 0.25f, t4.z * 0.25f, t4.w * 0.25f);
            float4 bk = bk4[p];
            s_pad += qv[p].x * bk.x + qv[p].y * bk.y + qv[p].z * bk.z + qv[p].w * bk.w;
        }
#pragma unroll
        for (int d = 0; d < 16; d++) accv[d] = 0.f;
        m = s_pad;
    }

    int cur = 0;
    for (int i = 0; i < nv; i++) {
        if (i + 1 < nv) {
            int e = vlist[i + 1];
            int nd = e >> 8, nh = (e >> 4) & 15, nw = e & 15;
#pragma unroll
            for (int j = 0; j < 6; j++) {
                int t = st_t[j];
                int vox = ((nd * 2 + (t >> 2)) * 32 + nh * 2 + ((t >> 1) & 1)) * 32 + nw * 2 + (t & 1);
                stg[j] = *(const float4*)&kv[(size_t)vox * HID + st_c4[j] * 4];
            }
        }

        if (active) {
#pragma unroll
            for (int t = 0; t < 8; t++) {
                const float4* kp4 = (const float4*)&kv_sh[cur][t * HID + h * HD];
                float4 k0 = kp4[0], k1 = kp4[1], k2 = kp4[2], k3 = kp4[3];
                float sc = qv[0].x * k0.x + qv[0].y * k0.y + qv[0].z * k0.z + qv[0].w * k0.w
                         + qv[1].x * k1.x + qv[1].y * k1.y + qv[1].z * k1.z + qv[1].w * k1.w
                         + qv[2].x * k2.x + qv[2].y * k2.y + qv[2].z * k2.z + qv[2].w * k2.w
                         + qv[3].x * k3.x + qv[3].y * k3.y + qv[3].z * k3.z + qv[3].w * k3.w;
                if (sc > m) {
                    float cf = __expf(m - sc);
                    l *= cf;
#pragma unroll
                    for (int d = 0; d < 16; d++) accv[d] *= cf;
                    m = sc;
                }
                float p = __expf(sc - m);
                l += p;
                const float4* vp4 = (const float4*)&kv_sh[cur][t * HID + DIM + h * HD];
#pragma unroll
                for (int pq = 0; pq < 4; pq++) {
                    float4 vv = vp4[pq];
                    accv[pq * 4 + 0] += p * vv.x;
                    accv[pq * 4 + 1] += p * vv.y;
                    accv[pq * 4 + 2] += p * vv.z;
                    accv[pq * 4 + 3] += p * vv.w;
                }
            }
        }
        __syncthreads();
        if (i + 1 < nv) {
#pragma unroll
            for (int j = 0; j < 6; j++)
                *(float4*)&kv_sh[cur ^ 1][st_t[j] * HID + st_c4[j] * 4] = stg[j];
        }
        __syncthreads();
        cur ^= 1;
    }

    if (active) {
        float pp = __expf(s_pad - m) * (8.f * (float)npad);
        l += pp;
        const float4* bv4 = (const float4*)&bkv[DIM + h * HD];
#pragma unroll
        for (int pq = 0; pq < 4; pq++) {
            float4 bv = bv4[pq];
            accv[pq * 4 + 0] += pp * bv.x;
            accv[pq * 4 + 1] += pp * bv.y;
            accv[pq * 4 + 2] += pp * bv.z;
            accv[pq * 4 + 3] += pp * bv.w;
        }
        float inv = 1.f / l;
        int vox = ((wd * 2 + (qi >> 2)) * 32 + wh * 2 + ((qi >> 1) & 1)) * 32 + ww * 2 + (qi & 1);
#pragma unroll
        for (int pq = 0; pq < 4; pq++) {
            float4 o = make_float4(accv[pq*4+0] * inv, accv[pq*4+1] * inv,
                                   accv[pq*4+2] * inv, accv[pq*4+3] * inv);
            *(float4*)&out[(size_t)vox * DIM + h * HD + pq * 4] = o;
        }
    }
}

// ---------------------------------------------------------------------------
extern "C" void kernel_launch(void* const* d_in, const int* in_sizes, int n_in,
                              void* d_out, int out_size)
{
    const float* x       = (const float*)d_in[0];
    const float* xa      = (const float*)d_in[1];
    const float* norm1_g = (const float*)d_in[2];
    const float* norm1_b = (const float*)d_in[3];
    const float* norm2_g = (const float*)d_in[4];
    const float* norm2_b = (const float*)d_in[5];
    const float* Wq      = (const float*)d_in[6];
    const float* bq      = (const float*)d_in[7];
    const float* Wkv     = (const float*)d_in[8];
    const float* bkv     = (const float*)d_in[9];
    const float* Wp      = (const float*)d_in[10];
    const float* bp      = (const float*)d_in[11];
    const float* W1      = (const float*)d_in[12];
    const float* b1      = (const float*)d_in[13];
    const float* W2      = (const float*)d_in[14];
    const float* b2      = (const float*)d_in[15];
    float* out = (float*)d_out;

    float* xn   = nullptr; float* xan  = nullptr; float* qb  = nullptr; float* kvb = nullptr;
    float* attn = nullptr; float* x1   = nullptr; float* x1n = nullptr; float* hb  = nullptr;
    cudaGetSymbolAddress((void**)&xn,   g_xn);
    cudaGetSymbolAddress((void**)&xan,  g_xan);
    cudaGetSymbolAddress((void**)&qb,   g_q);
    cudaGetSymbolAddress((void**)&kvb,  g_kv);
    cudaGetSymbolAddress((void**)&attn, g_attn);
    cudaGetSymbolAddress((void**)&x1,   g_x1);
    cudaGetSymbolAddress((void**)&x1n,  g_x1n);
    cudaGetSymbolAddress((void**)&hb,   g_h);

    const int ln_blocks = TOKENS / 8;

    ln_kernel<<<ln_blocks, 256>>>(x,  norm1_g, norm1_b, xn,  TOKENS);
    ln_kernel<<<ln_blocks, 256>>>(xa, norm1_g, norm1_b, xan, TOKENS);

    gemm_tc<false, false><<<dim3(DIM / 96, TOKENS / 128), 128>>>(xn,  Wq,  bq,  nullptr, qb,  TOKENS, DIM, DIM);
    gemm_tc<false, false><<<dim3(HID / 96, TOKENS / 128), 128>>>(xan, Wkv, bkv, nullptr, kvb, TOKENS, HID, DIM);

    attn_kernel<<<4096, 128>>>(qb, kvb, bkv, attn);

    gemm_tc<true, false><<<dim3(DIM / 96, TOKENS / 128), 128>>>(attn, Wp, bp, x, x1, TOKENS, DIM, DIM);

    ln_kernel<<<ln_blocks, 256>>>(x1, norm2_g, norm2_b, x1n, TOKENS);

    gemm_tc<false, true><<<dim3(HID / 96, TOKENS / 128), 128>>>(x1n, W1, b1, nullptr, hb, TOKENS, HID, DIM);
    gemm_tc<true, false><<<dim3(DIM / 96, TOKENS / 128), 128>>>(hb, W2, b2, x1, out, TOKENS, DIM, HID);
}

// round 7
// speedup vs baseline: 2.6220x; 1.1752x over previous
#include <cuda_runtime.h>
#include <cuda_bf16.h>
#include <math.h>

// ---------------------------------------------------------------------------
// CrossTransformerBlock3D: 32x32x32 voxels, DIM=192, 12 heads x 16, WS=(2,2,2)
// GEMMs: tf32 mma.m16n8k8, 128x96 block tile, cp.async double-buffered.
// Attention: kv stored bf16, f32x2 packed FMA inner loop, triple-buffered slabs.
// ---------------------------------------------------------------------------

#define TOKENS 32768
#define DIM 192
#define HID 384
#define HEADS 12
#define HD 16

__device__ float g_xn  [TOKENS * DIM];
__device__ float g_xan [TOKENS * DIM];
__device__ float g_q   [TOKENS * DIM];
__device__ __nv_bfloat16 g_kv[TOKENS * HID];
__device__ float g_attn[TOKENS * DIM];
__device__ float g_x1  [TOKENS * DIM];
__device__ float g_x1n [TOKENS * DIM];
__device__ float g_h   [TOKENS * HID];

typedef unsigned long long u64;
__device__ __forceinline__ u64 fma2(u64 a, u64 b, u64 c)
{
    u64 d; asm("fma.rn.f32x2 %0,%1,%2,%3;" : "=l"(d) : "l"(a), "l"(b), "l"(c)); return d;
}
__device__ __forceinline__ u64 pack2(float lo, float hi)
{
    u64 d; asm("mov.b64 %0,{%1,%2};" : "=l"(d) : "f"(lo), "f"(hi)); return d;
}
__device__ __forceinline__ float2 unpack2(u64 v)
{
    float lo, hi; asm("mov.b64 {%0,%1},%2;" : "=f"(lo), "=f"(hi) : "l"(v));
    return make_float2(lo, hi);
}

// --------------------------- LayerNorm (warp per row, C=192) ----------------
__global__ void ln_kernel(const float* __restrict__ x, const float* __restrict__ g,
                          const float* __restrict__ b, float* __restrict__ o, int rows)
{
    int warp = (blockIdx.x * blockDim.x + threadIdx.x) >> 5;
    int lane = threadIdx.x & 31;
    if (warp >= rows) return;
    const float* xr = x + (size_t)warp * DIM;
    float v[6];
    float s = 0.f, s2 = 0.f;
#pragma unroll
    for (int i = 0; i < 6; i++) {
        v[i] = xr[lane + i * 32];
        s += v[i];
        s2 += v[i] * v[i];
    }
#pragma unroll
    for (int off = 16; off; off >>= 1) {
        s  += __shfl_xor_sync(0xffffffffu, s,  off);
        s2 += __shfl_xor_sync(0xffffffffu, s2, off);
    }
    float mean = s * (1.f / DIM);
    float var  = s2 * (1.f / DIM) - mean * mean;
    float rstd = rsqrtf(var + 1e-5f);
    float* orow = o + (size_t)warp * DIM;
#pragma unroll
    for (int i = 0; i < 6; i++) {
        int c = lane + i * 32;
        orow[c] = (v[i] - mean) * rstd * g[c] + b[c];
    }
}

// --------------------------- cp.async helpers -------------------------------
__device__ __forceinline__ void cp16(void* dst_smem, const void* src)
{
    unsigned d = (unsigned)__cvta_generic_to_shared(dst_smem);
    asm volatile("cp.async.ca.shared.global [%0], [%1], 16;" :: "r"(d), "l"(src));
}
#define CP_COMMIT asm volatile("cp.async.commit_group;")
#define CP_WAIT0  asm volatile("cp.async.wait_group 0;")

// --------------------------- tf32 tensor-core GEMM --------------------------
#define MMA_TF32(d, a, b)                                                     \
    asm volatile("mma.sync.aligned.m16n8k8.row.col.f32.tf32.tf32.f32 "        \
                 "{%0,%1,%2,%3}, {%4,%5,%6,%7}, {%8,%9}, {%0,%1,%2,%3};"      \
                 : "+f"(d[0]), "+f"(d[1]), "+f"(d[2]), "+f"(d[3])             \
                 : "r"(a[0]), "r"(a[1]), "r"(a[2]), "r"(a[3]),                \
                   "r"(b[0]), "r"(b[1]))

template <bool RES, bool GELU, bool OB>
__global__ __launch_bounds__(128, 3) void gemm_tc(const float* __restrict__ A,
                                                  const float* __restrict__ B,
                                                  const float* __restrict__ bias,
                                                  const float* __restrict__ resid,
                                                  void* __restrict__ Cv,
                                                  int M, int N, int K)
{
    __shared__ __align__(16) float As[2][128][20];
    __shared__ __align__(16) float Bs[2][16][104];

    const int tid = threadIdx.x;
    const int bm = blockIdx.y * 128;
    const int bn = blockIdx.x * 96;
    const int lane = tid & 31, w = tid >> 5;
    const int g = lane >> 2, tg = lane & 3;
    const int wr = (w & 1) * 64;
    const int wc = (w >> 1) * 48;

    float acc[4][6][4];
#pragma unroll
    for (int mi = 0; mi < 4; mi++)
#pragma unroll
        for (int ni = 0; ni < 6; ni++)
#pragma unroll
            for (int r = 0; r < 4; r++) acc[mi][ni][r] = 0.f;

    const int nchunks = K >> 4;

    {
#pragma unroll
        for (int i = 0; i < 4; i++) {
            int f = tid + i * 128;
            int r = f >> 2, c4 = (f & 3) * 4;
            cp16(&As[0][r][c4], &A[(size_t)(bm + r) * K + c4]);
        }
#pragma unroll
        for (int i = 0; i < 3; i++) {
            int f = tid + i * 128;
            int kr = f / 24, nq = (f % 24) * 4;
            cp16(&Bs[0][kr][nq], &B[(size_t)kr * N + bn + nq]);
        }
        CP_COMMIT;
    }

    int s = 0;
    for (int ci = 0; ci < nchunks; ci++, s ^= 1) {
        CP_WAIT0;
        __syncthreads();

        if (ci + 1 < nchunks) {
            int k0 = (ci + 1) << 4;
#pragma unroll
            for (int i = 0; i < 4; i++) {
                int f = tid + i * 128;
                int r = f >> 2, c4 = (f & 3) * 4;
                cp16(&As[s ^ 1][r][c4], &A[(size_t)(bm + r) * K + k0 + c4]);
            }
#pragma unroll
            for (int i = 0; i < 3; i++) {
                int f = tid + i * 128;
                int kr = f / 24, nq = (f % 24) * 4;
                cp16(&Bs[s ^ 1][kr][nq], &B[(size_t)(k0 + kr) * N + bn + nq]);
            }
            CP_COMMIT;
        }

#pragma unroll
        for (int kk = 0; kk < 2; kk++) {
            unsigned a[4][4], b[6][2];
#pragma unroll
            for (int mi = 0; mi < 4; mi++) {
                int r = wr + mi * 16 + g;
                a[mi][0] = __float_as_uint(As[s][r    ][kk * 8 + tg]);
                a[mi][1] = __float_as_uint(As[s][r + 8][kk * 8 + tg]);
                a[mi][2] = __float_as_uint(As[s][r    ][kk * 8 + tg + 4]);
                a[mi][3] = __float_as_uint(As[s][r + 8][kk * 8 + tg + 4]);
            }
#pragma unroll
            for (int ni = 0; ni < 6; ni++) {
                int n = wc + ni * 8 + g;
                b[ni][0] = __float_as_uint(Bs[s][kk * 8 + tg    ][n]);
                b[ni][1] = __float_as_uint(Bs[s][kk * 8 + tg + 4][n]);
            }
#pragma unroll
            for (int mi = 0; mi < 4; mi++)
#pragma unroll
                for (int ni = 0; ni < 6; ni++)
                    MMA_TF32(acc[mi][ni], a[mi], b[ni]);
        }
        __syncthreads();
    }

    float* Cf = (float*)Cv;
    __nv_bfloat16* Cb = (__nv_bfloat16*)Cv;
#pragma unroll
    for (int mi = 0; mi < 4; mi++) {
#pragma unroll
        for (int ni = 0; ni < 6; ni++) {
            int col = bn + wc + ni * 8 + tg * 2;
            float b0 = bias[col], b1 = bias[col + 1];
#pragma unroll
            for (int half = 0; half < 2; half++) {
                int row = bm + wr + mi * 16 + g + half * 8;
                float v0 = acc[mi][ni][half * 2 + 0] + b0;
                float v1 = acc[mi][ni][half * 2 + 1] + b1;
                if (GELU) {
                    v0 = 0.5f * v0 * (1.f + erff(v0 * 0.70710678118654752f));
                    v1 = 0.5f * v1 * (1.f + erff(v1 * 0.70710678118654752f));
                }
                if (RES) {
                    v0 += resid[(size_t)row * N + col];
                    v1 += resid[(size_t)row * N + col + 1];
                }
                if (OB) {
                    *(__nv_bfloat162*)&Cb[(size_t)row * N + col] = __floats2bfloat162_rn(v0, v1);
                } else {
                    *(float2*)&Cf[(size_t)row * N + col] = make_float2(v0, v1);
                }
            }
        }
    }
}

// --------------------------- windowed cross attention -----------------------
// Block = 1 window, 128 threads. Active 96 threads = (head, query).
// kv: bf16 global, converted to fp32 at staging. Triple-buffered, 1 sync/slab.
// Sum-only softmax with fixed shift m = s_pad (scores bounded, shift-invariant).
__global__ __launch_bounds__(128) void attn_kernel(const float* __restrict__ q,
                                                   const __nv_bfloat16* __restrict__ kv,
                                                   const float* __restrict__ bkv,
                                                   float* __restrict__ out)
{
    __shared__ float kv_sh[3][8 * HID];       // 36 KB

    const int bid = blockIdx.x;
    const int wd = bid >> 8, wh = (bid >> 4) & 15, ww = bid & 15;
    const int tid = threadIdx.x;

    // valid neighbor slabs
    int vlist[26], nv = 0, npad = 0;
#pragma unroll
    for (int sl = 0; sl < 27; sl++) {
        int nd = wd + sl / 9 - 1;
        int nh = wh + (sl / 3) % 3 - 1;
        int nw = ww + sl % 3 - 1;
        bool valid = (sl != 20) && (unsigned)nd < 16u && (unsigned)nh < 16u && (unsigned)nw < 16u;
        if (valid) vlist[nv++] = (nd << 8) | (nh << 4) | nw;
        else       npad++;
    }

    // staging lanes: 3 x 16B (8 bf16) chunks per thread per slab
    int st_t[3], st_c8[3];
#pragma unroll
    for (int j = 0; j < 3; j++) {
        int f = tid + j * 128;            // 0..383
        st_t[j] = f / 48;
        st_c8[j] = f % 48;
    }

    // q into registers (active threads), packed f32x2
    const int h = tid >> 3, qi = tid & 7;
    const bool active = tid < 96;
    u64 qp[8], av[8];
    float l = 0.f, s_pad = 0.f;
    int voxq = 0;
    if (active) {
        voxq = ((wd * 2 + (qi >> 2)) * 32 + wh * 2 + ((qi >> 1) & 1)) * 32 + ww * 2 + (qi & 1);
        const float2* q2 = (const float2*)&q[(size_t)voxq * DIM + h * HD];
        const float2* bk2 = (const float2*)&bkv[h * HD];
#pragma unroll
        for (int p = 0; p < 8; p++) {
            float2 t2 = q2[p];
            float2 bk = bk2[p];
            t2.x *= 0.25f; t2.y *= 0.25f;
            s_pad += t2.x * bk.x + t2.y * bk.y;
            qp[p] = pack2(t2.x, t2.y);
            av[p] = pack2(0.f, 0.f);
        }
    }

    // preload slab 0
    uint4 stg[3];
    {
        int e = vlist[0];
        int nd = e >> 8, nh = (e >> 4) & 15, nw = e & 15;
#pragma unroll
        for (int j = 0; j < 3; j++) {
            int t = st_t[j];
            int vox = ((nd * 2 + (t >> 2)) * 32 + nh * 2 + ((t >> 1) & 1)) * 32 + nw * 2 + (t & 1);
            stg[j] = *(const uint4*)&kv[(size_t)vox * HID + st_c8[j] * 8];
        }
#pragma unroll
        for (int j = 0; j < 3; j++) {
            const __nv_bfloat162* hb = (const __nv_bfloat162*)&stg[j];
            float* dst = &kv_sh[0][st_t[j] * HID + st_c8[j] * 8];
            float2 f0 = __bfloat1622float2(hb[0]);
            float2 f1 = __bfloat1622float2(hb[1]);
            float2 f2 = __bfloat1622float2(hb[2]);
            float2 f3 = __bfloat1622float2(hb[3]);
            *(float4*)dst       = make_float4(f0.x, f0.y, f1.x, f1.y);
            *(float4*)(dst + 4) = make_float4(f2.x, f2.y, f3.x, f3.y);
        }
    }
    __syncthreads();

    for (int i = 0; i < nv; i++) {
        const int rbuf = i % 3, wbuf = (i + 1) % 3;

        // prefetch next slab to registers
        if (i + 1 < nv) {
            int e = vlist[i + 1];
            int nd = e >> 8, nh = (e >> 4) & 15, nw = e & 15;
#pragma unroll
            for (int j = 0; j < 3; j++) {
                int t = st_t[j];
                int vox = ((nd * 2 + (t >> 2)) * 32 + nh * 2 + ((t >> 1) & 1)) * 32 + nw * 2 + (t & 1);
                stg[j] = *(const uint4*)&kv[(size_t)vox * HID + st_c8[j] * 8];
            }
        }

        if (active) {
#pragma unroll
            for (int t = 0; t < 8; t++) {
                const u64* kp = (const u64*)&kv_sh[rbuf][t * HID + h * HD];
                u64 s2 = pack2(0.f, 0.f);
#pragma unroll
                for (int p = 0; p < 8; p++) s2 = fma2(qp[p], kp[p], s2);
                float2 sh = unpack2(s2);
                float pw = __expf(sh.x + sh.y - s_pad);
                l += pw;
                u64 p2 = pack2(pw, pw);
                const u64* vp = (const u64*)&kv_sh[rbuf][t * HID + DIM + h * HD];
#pragma unroll
                for (int p = 0; p < 8; p++) av[p] = fma2(p2, vp[p], av[p]);
            }
        }

        // stage next slab into wbuf
        if (i + 1 < nv) {
#pragma unroll
            for (int j = 0; j < 3; j++) {
                const __nv_bfloat162* hb = (const __nv_bfloat162*)&stg[j];
                float* dst = &kv_sh[wbuf][st_t[j] * HID + st_c8[j] * 8];
                float2 f0 = __bfloat1622float2(hb[0]);
                float2 f1 = __bfloat1622float2(hb[1]);
                float2 f2 = __bfloat1622float2(hb[2]);
                float2 f3 = __bfloat1622float2(hb[3]);
                *(float4*)dst       = make_float4(f0.x, f0.y, f1.x, f1.y);
                *(float4*)(dst + 4) = make_float4(f2.x, f2.y, f3.x, f3.y);
            }
        }
        __syncthreads();
    }

    if (active) {
        float pp = 8.f * (float)npad;     // exp(s_pad - s_pad) = 1 per padded key
        l += pp;
        const float2* bv2 = (const float2*)&bkv[DIM + h * HD];
        float inv = 1.f / l;
        float* orow = &out[(size_t)voxq * DIM + h * HD];
#pragma unroll
        for (int p = 0; p < 8; p++) {
            float2 a2 = unpack2(av[p]);
            float2 bv = bv2[p];
            *(float2*)&orow[p * 2] = make_float2((a2.x + pp * bv.x) * inv,
                                                 (a2.y + pp * bv.y) * inv);
        }
    }
}

// ---------------------------------------------------------------------------
extern "C" void kernel_launch(void* const* d_in, const int* in_sizes, int n_in,
                              void* d_out, int out_size)
{
    const float* x       = (const float*)d_in[0];
    const float* xa      = (const float*)d_in[1];
    const float* norm1_g = (const float*)d_in[2];
    const float* norm1_b = (const float*)d_in[3];
    const float* norm2_g = (const float*)d_in[4];
    const float* norm2_b = (const float*)d_in[5];
    const float* Wq      = (const float*)d_in[6];
    const float* bq      = (const float*)d_in[7];
    const float* Wkv     = (const float*)d_in[8];
    const float* bkv     = (const float*)d_in[9];
    const float* Wp      = (const float*)d_in[10];
    const float* bp      = (const float*)d_in[11];
    const float* W1      = (const float*)d_in[12];
    const float* b1      = (const float*)d_in[13];
    const float* W2      = (const float*)d_in[14];
    const float* b2      = (const float*)d_in[15];
    float* out = (float*)d_out;

    float* xn = nullptr; float* xan = nullptr; float* qb = nullptr;
    __nv_bfloat16* kvb = nullptr;
    float* attn = nullptr; float* x1 = nullptr; float* x1n = nullptr; float* hb = nullptr;
    cudaGetSymbolAddress((void**)&xn,   g_xn);
    cudaGetSymbolAddress((void**)&xan,  g_xan);
    cudaGetSymbolAddress((void**)&qb,   g_q);
    cudaGetSymbolAddress((void**)&kvb,  g_kv);
    cudaGetSymbolAddress((void**)&attn, g_attn);
    cudaGetSymbolAddress((void**)&x1,   g_x1);
    cudaGetSymbolAddress((void**)&x1n,  g_x1n);
    cudaGetSymbolAddress((void**)&hb,   g_h);

    const int ln_blocks = TOKENS / 8;

    ln_kernel<<<ln_blocks, 256>>>(x,  norm1_g, norm1_b, xn,  TOKENS);
    ln_kernel<<<ln_blocks, 256>>>(xa, norm1_g, norm1_b, xan, TOKENS);

    gemm_tc<false, false, false><<<dim3(DIM / 96, TOKENS / 128), 128>>>(xn,  Wq,  bq,  nullptr, qb,  TOKENS, DIM, DIM);
    gemm_tc<false, false, true ><<<dim3(HID / 96, TOKENS / 128), 128>>>(xan, Wkv, bkv, nullptr, kvb, TOKENS, HID, DIM);

    attn_kernel<<<4096, 128>>>(qb, kvb, bkv, attn);

    gemm_tc<true, false, false><<<dim3(DIM / 96, TOKENS / 128), 128>>>(attn, Wp, bp, x, x1, TOKENS, DIM, DIM);

    ln_kernel<<<ln_blocks, 256>>>(x1, norm2_g, norm2_b, x1n, TOKENS);

    gemm_tc<false, true, false><<<dim3(HID / 96, TOKENS / 128), 128>>>(x1n, W1, b1, nullptr, hb, TOKENS, HID, DIM);
    gemm_tc<true, false, false><<<dim3(DIM / 96, TOKENS / 128), 128>>>(hb, W2, b2, x1, out, TOKENS, DIM, HID);
}